// round 2
// baseline (speedup 1.0000x reference)
#include <cuda_runtime.h>
#include <cstdint>

// ---------------------------------------------------------------------------
// WindowAttention (Swin) — fp32, FFMA2 (fma.rn.f32x2) packed math
//   B_WIN=2048, N_TOK=49, DIM=512, HEADS=16, hd=32, NW=64
// Pipeline: bias gather -> QKV GEMM (scatter to q/k/v) -> per-(b,h) attention
//           -> proj GEMM -> d_out
// ---------------------------------------------------------------------------

#define M_TOTAL   100352          // 2048*49
#define KDIM      512
#define NQKV      1536
#define NPROJ     512
#define HEADS     16
#define NTOK      49
#define HD        32
#define SCALE_Q   0.17677669529663687f   // 32^-0.5

// scratch (allocation-free rule: __device__ globals)
__device__ float g_q[2048u * 16 * 49 * 32];     // [B*H][49][32]
__device__ float g_k[2048u * 16 * 49 * 32];
__device__ float g_v[2048u * 16 * 49 * 32];
__device__ float g_att[2048u * 49 * 512];       // [B][49][C]  (C = h*32+d)
__device__ float g_hbias[16 * 49 * 49];         // [H][49][49]

// ---- packed f32x2 helpers --------------------------------------------------
__device__ __forceinline__ unsigned long long ffma2(unsigned long long a,
                                                    unsigned long long b,
                                                    unsigned long long c) {
    unsigned long long d;
    asm("fma.rn.f32x2 %0, %1, %2, %3;" : "=l"(d) : "l"(a), "l"(b), "l"(c));
    return d;
}
__device__ __forceinline__ unsigned long long pack2(float x, float y) {
    unsigned long long d;
    asm("mov.b64 %0, {%1, %2};" : "=l"(d) : "f"(x), "f"(y));
    return d;
}
__device__ __forceinline__ float lo32(unsigned long long v) {
    return __uint_as_float((unsigned)(v & 0xffffffffull));
}
__device__ __forceinline__ float hi32(unsigned long long v) {
    return __uint_as_float((unsigned)(v >> 32));
}

// ---------------------------------------------------------------------------
// 1. relative-position bias gather:  g_hbias[h][i][j] = bias_table[rel_index[i][j]][h]
// ---------------------------------------------------------------------------
__global__ void bias_kernel(const float* __restrict__ bt, const int* __restrict__ ri) {
    int idx = blockIdx.x * 256 + threadIdx.x;           // over 16*2401
    if (idx < 16 * 2401) {
        int h  = idx / 2401;
        int ij = idx - h * 2401;
        g_hbias[idx] = bt[ri[ij] * 16 + h];
    }
}

// ---------------------------------------------------------------------------
// 2/4. GEMM  C[M,N] = A[M,512] @ W[N,512]^T + bias
//   MODE 0: A = x,     N=1536, scatter epilogue into g_q/g_k/g_v (q scaled)
//   MODE 1: A = g_att, N=512,  plain epilogue into Cout
// BM=BN=128, BK=16, 256 threads, 8x8 micro-tile held as 8 x (4 f32x2).
// ---------------------------------------------------------------------------
template <int MODE>
__global__ __launch_bounds__(256) void gemm_kernel(const float* __restrict__ Ain,
                                                   const float* __restrict__ W,
                                                   const float* __restrict__ bias,
                                                   float* __restrict__ Cout) {
    __shared__ __align__(16) float As[16][132];   // [k][m], padded row stride
    __shared__ __align__(16) float Bs[16][132];   // [k][n]

    const float* A = (MODE == 1) ? (const float*)g_att : Ain;

    const int tid = threadIdx.x;
    const int m0  = blockIdx.y * 128;
    const int n0  = blockIdx.x * 128;

    // global-load mapping: 512 float4 per tile, 2 per thread (same row, adjacent c4)
    const int r0 = tid >> 1;
    const int c0 = (tid & 1) * 2;
    const int c1 = c0 + 1;

    const float* ap0 = A + (size_t)(m0 + r0) * KDIM + c0 * 4;
    const float* ap1 = A + (size_t)(m0 + r0) * KDIM + c1 * 4;
    const float* bp0 = W + (size_t)(n0 + r0) * KDIM + c0 * 4;
    const float* bp1 = W + (size_t)(n0 + r0) * KDIM + c1 * 4;

    const int m_off = (tid >> 4) * 8;
    const int n_off = (tid & 15) * 8;

    unsigned long long c[8][4];
#pragma unroll
    for (int i = 0; i < 8; i++)
#pragma unroll
        for (int j = 0; j < 4; j++) c[i][j] = 0ull;

    float4 ra0 = *(const float4*)(ap0);
    float4 ra1 = *(const float4*)(ap1);
    float4 rb0 = *(const float4*)(bp0);
    float4 rb1 = *(const float4*)(bp1);

#define STORE_TILES()                                                                   \
    do {                                                                                \
        As[c0 * 4 + 0][r0] = ra0.x; As[c0 * 4 + 1][r0] = ra0.y;                         \
        As[c0 * 4 + 2][r0] = ra0.z; As[c0 * 4 + 3][r0] = ra0.w;                         \
        As[c1 * 4 + 0][r0] = ra1.x; As[c1 * 4 + 1][r0] = ra1.y;                         \
        As[c1 * 4 + 2][r0] = ra1.z; As[c1 * 4 + 3][r0] = ra1.w;                         \
        Bs[c0 * 4 + 0][r0] = rb0.x; Bs[c0 * 4 + 1][r0] = rb0.y;                         \
        Bs[c0 * 4 + 2][r0] = rb0.z; Bs[c0 * 4 + 3][r0] = rb0.w;                         \
        Bs[c1 * 4 + 0][r0] = rb1.x; Bs[c1 * 4 + 1][r0] = rb1.y;                         \
        Bs[c1 * 4 + 2][r0] = rb1.z; Bs[c1 * 4 + 3][r0] = rb1.w;                         \
    } while (0)

    STORE_TILES();
    __syncthreads();

    const int KTILES = KDIM / 16;   // 32
    for (int kt = 0; kt < KTILES; kt++) {
        if (kt < KTILES - 1) {
            int ko = (kt + 1) * 16;
            ra0 = *(const float4*)(ap0 + ko);
            ra1 = *(const float4*)(ap1 + ko);
            rb0 = *(const float4*)(bp0 + ko);
            rb1 = *(const float4*)(bp1 + ko);
        }
#pragma unroll
        for (int k = 0; k < 16; k++) {
            float4 a0 = *(const float4*)&As[k][m_off];
            float4 a1 = *(const float4*)&As[k][m_off + 4];
            ulonglong2 b0 = *(const ulonglong2*)&Bs[k][n_off];
            ulonglong2 b1 = *(const ulonglong2*)&Bs[k][n_off + 4];
            float av[8] = {a0.x, a0.y, a0.z, a0.w, a1.x, a1.y, a1.z, a1.w};
#pragma unroll
            for (int i = 0; i < 8; i++) {
                unsigned long long aa = pack2(av[i], av[i]);
                c[i][0] = ffma2(aa, b0.x, c[i][0]);
                c[i][1] = ffma2(aa, b0.y, c[i][1]);
                c[i][2] = ffma2(aa, b1.x, c[i][2]);
                c[i][3] = ffma2(aa, b1.y, c[i][3]);
            }
        }
        __syncthreads();
        if (kt < KTILES - 1) {
            STORE_TILES();
            __syncthreads();
        }
    }
#undef STORE_TILES

    // epilogue
#pragma unroll
    for (int i = 0; i < 8; i++) {
        int m = m0 + m_off + i;
        int b = 0, tok = 0;
        if (MODE == 0) { b = m / NTOK; tok = m - b * NTOK; }
#pragma unroll
        for (int jp = 0; jp < 4; jp++) {
            int n = n0 + n_off + jp * 2;                 // n even; n,n+1 same (s,h)
            float v0 = lo32(c[i][jp]) + bias[n];
            float v1 = hi32(c[i][jp]) + bias[n + 1];
            if (MODE == 0) {
                int s = n >> 9;
                int h = (n >> 5) & 15;
                int d = n & 31;
                float* dst = (s == 0) ? g_q : (s == 1) ? g_k : g_v;
                float sc   = (s == 0) ? SCALE_Q : 1.0f;
                size_t base = (((size_t)b * HEADS + h) * NTOK + tok) * HD + d;
                dst[base]     = v0 * sc;
                dst[base + 1] = v1 * sc;
            } else {
                Cout[(size_t)m * NPROJ + n]     = v0;
                Cout[(size_t)m * NPROJ + n + 1] = v1;
            }
        }
    }
}

// ---------------------------------------------------------------------------
// 3. attention: one CTA per (b,h); thread i owns query row i (i<49).
// ---------------------------------------------------------------------------
__global__ __launch_bounds__(64) void attn_kernel(const float* __restrict__ mask) {
    __shared__ __align__(16) float ks[NTOK * HD];
    __shared__ __align__(16) float vs[NTOK * HD];

    int bh = blockIdx.x;          // b*16 + h
    int b  = bh >> 4;
    int h  = bh & 15;
    int w  = b & 63;              // window index within image

    size_t base = (size_t)bh * (NTOK * HD);
    {
        const float4* kg = (const float4*)(g_k + base);
        const float4* vg = (const float4*)(g_v + base);
        float4* ks4 = (float4*)ks;
        float4* vs4 = (float4*)vs;
        for (int t = threadIdx.x; t < (NTOK * HD) / 4; t += 64) {
            ks4[t] = kg[t];
            vs4[t] = vg[t];
        }
    }
    __syncthreads();

    int i = threadIdx.x;
    if (i >= NTOK) return;

    unsigned long long q2[16];    // 32 q floats as 16 f32x2
    {
        const ulonglong2* qp = (const ulonglong2*)(g_q + base + (size_t)i * HD);
#pragma unroll
        for (int t = 0; t < 8; t++) {
            ulonglong2 u = qp[t];
            q2[2 * t]     = u.x;
            q2[2 * t + 1] = u.y;
        }
    }

    const float* bb = g_hbias + (h * (NTOK * NTOK) + i * NTOK);
    const float* mm = mask + ((size_t)w * NTOK + i) * NTOK;

    float s[NTOK];
#pragma unroll
    for (int j = 0; j < NTOK; j++) {
        const ulonglong2* kr = (const ulonglong2*)(ks + j * HD);
        unsigned long long a0 = 0, a1 = 0, a2 = 0, a3 = 0;
#pragma unroll
        for (int t = 0; t < 4; t++) {
            ulonglong2 k0 = kr[2 * t];
            ulonglong2 k1 = kr[2 * t + 1];
            a0 = ffma2(q2[4 * t + 0], k0.x, a0);
            a1 = ffma2(q2[4 * t + 1], k0.y, a1);
            a2 = ffma2(q2[4 * t + 2], k1.x, a2);
            a3 = ffma2(q2[4 * t + 3], k1.y, a3);
        }
        float r = (lo32(a0) + hi32(a0)) + (lo32(a1) + hi32(a1)) +
                  (lo32(a2) + hi32(a2)) + (lo32(a3) + hi32(a3));
        s[j] = r + __ldg(bb + j) + __ldg(mm + j);
    }

    float mx = s[0];
#pragma unroll
    for (int j = 1; j < NTOK; j++) mx = fmaxf(mx, s[j]);
    float sum = 0.0f;
#pragma unroll
    for (int j = 0; j < NTOK; j++) {
        float e = __expf(s[j] - mx);
        s[j] = e;
        sum += e;
    }
    float inv = 1.0f / sum;

    unsigned long long o2[16];
#pragma unroll
    for (int t = 0; t < 16; t++) o2[t] = 0ull;
#pragma unroll
    for (int j = 0; j < NTOK; j++) {
        unsigned long long pp = pack2(s[j], s[j]);
        const ulonglong2* vr = (const ulonglong2*)(vs + j * HD);
#pragma unroll
        for (int t = 0; t < 8; t++) {
            ulonglong2 vv = vr[t];
            o2[2 * t]     = ffma2(pp, vv.x, o2[2 * t]);
            o2[2 * t + 1] = ffma2(pp, vv.y, o2[2 * t + 1]);
        }
    }

    float* og = g_att + ((size_t)(b * NTOK + i)) * 512 + h * HD;
#pragma unroll
    for (int t = 0; t < 8; t++) {
        float4 f;
        f.x = lo32(o2[2 * t]) * inv;
        f.y = hi32(o2[2 * t]) * inv;
        f.z = lo32(o2[2 * t + 1]) * inv;
        f.w = hi32(o2[2 * t + 1]) * inv;
        *(float4*)(og + 4 * t) = f;
    }
}

// ---------------------------------------------------------------------------
extern "C" void kernel_launch(void* const* d_in, const int* in_sizes, int n_in,
                              void* d_out, int out_size) {
    const float* x          = (const float*)d_in[0];
    const float* w_qkv      = (const float*)d_in[1];
    const float* b_qkv      = (const float*)d_in[2];
    const float* w_proj     = (const float*)d_in[3];
    const float* b_proj     = (const float*)d_in[4];
    const float* bias_table = (const float*)d_in[5];
    const int*   rel_index  = (const int*)d_in[6];
    const float* mask       = (const float*)d_in[7];
    float* out = (float*)d_out;

    bias_kernel<<<(16 * 2401 + 255) / 256, 256>>>(bias_table, rel_index);
    gemm_kernel<0><<<dim3(NQKV / 128, M_TOTAL / 128), 256>>>(x, w_qkv, b_qkv, nullptr);
    attn_kernel<<<2048 * 16, 64>>>(mask);
    gemm_kernel<1><<<dim3(NPROJ / 128, M_TOTAL / 128), 256>>>(nullptr, w_proj, b_proj, out);
}